// round 4
// baseline (speedup 1.0000x reference)
#include <cuda_runtime.h>
#include <cstdint>

#define N_NODES 100000
#define D_IN    512
#define D_H     128
#define NH      (N_NODES * D_H)
#define N_EDGES 1600000

__device__ __align__(16) float g_h[NH];
__device__ __align__(16) float g_vals[N_EDGES];
__device__ double g_sum[D_H];
__device__ double g_sumsq[D_H];
__device__ float  g_scale[D_H];
__device__ float  g_shift[D_H];

__host__ __device__ __forceinline__ void tf2x32(unsigned k0, unsigned k1,
                                                unsigned &x0, unsigned &x1) {
  unsigned k2 = k0 ^ k1 ^ 0x1BD11BDAu;
  x0 += k0; x1 += k1;
#define TFR(r) { x0 += x1; x1 = (x1 << (r)) | (x1 >> (32 - (r))); x1 ^= x0; }
  TFR(13) TFR(15) TFR(26) TFR(6)   x0 += k1; x1 += k2 + 1u;
  TFR(17) TFR(29) TFR(16) TFR(24)  x0 += k2; x1 += k0 + 2u;
  TFR(13) TFR(15) TFR(26) TFR(6)   x0 += k0; x1 += k1 + 3u;
  TFR(17) TFR(29) TFR(16) TFR(24)  x0 += k1; x1 += k2 + 4u;
  TFR(13) TFR(15) TFR(26) TFR(6)   x0 += k2; x1 += k0 + 5u;
#undef TFR
}

__device__ __forceinline__ unsigned rbits32(unsigned k0, unsigned k1, unsigned i) {
  unsigned x0 = 0u, x1 = i;
  tf2x32(k0, k1, x0, x1);
  return x0 ^ x1;
}

__device__ __forceinline__ float u01(unsigned b) {
  return __uint_as_float((b >> 9) | 0x3F800000u) - 1.0f;
}

__device__ __forceinline__ float erfinv_xla(float x) {
  float w = -log1pf(-x * x);
  float p;
  if (w < 5.0f) {
    w -= 2.5f;
    p = 2.81022636e-08f;
    p = fmaf(p, w, 3.43273939e-07f);
    p = fmaf(p, w, -3.5233877e-06f);
    p = fmaf(p, w, -4.39150654e-06f);
    p = fmaf(p, w, 0.00021858087f);
    p = fmaf(p, w, -0.00125372503f);
    p = fmaf(p, w, -0.00417768164f);
    p = fmaf(p, w, 0.246640727f);
    p = fmaf(p, w, 1.50140941f);
  } else {
    w = sqrtf(w) - 3.0f;
    p = -0.000200214257f;
    p = fmaf(p, w, 0.000100950558f);
    p = fmaf(p, w, 0.00134934322f);
    p = fmaf(p, w, -0.00367342844f);
    p = fmaf(p, w, 0.00573950773f);
    p = fmaf(p, w, -0.0076224613f);
    p = fmaf(p, w, 0.00943887047f);
    p = fmaf(p, w, 1.00167406f);
    p = fmaf(p, w, 2.83297682f);
  }
  return p * x;
}

__device__ __forceinline__ float normal32(unsigned b) {
  const float LO = -0.99999994f;
  float f = u01(b);
  float u = fmaxf(LO, f * 2.0f + LO);
  return 1.4142135381698608f * erfinv_xla(u);
}

// x = (data + 0.01*N(kn)) * keep(ka) * keep(kb) * 4   computed on the fly
__device__ __forceinline__ float gen_x(const float dv, unsigned i,
                                       unsigned kn0, unsigned kn1,
                                       unsigned ka0, unsigned ka1,
                                       unsigned kb0, unsigned kb1) {
  unsigned b1 = rbits32(ka0, ka1, i);
  unsigned b2 = rbits32(kb0, kb1, i);
  // bernoulli(0.5) keep  <=>  u01(b) < 0.5  <=>  top bit of b is 0
  if (((b1 | b2) & 0x80000000u) == 0u) {
    float n = normal32(rbits32(kn0, kn1, i));
    return (dv + 0.01f * n) * 4.0f;
  }
  return 0.0f;
}

__global__ void zero_stats_kernel() {
  g_sum[threadIdx.x] = 0.0;
  g_sumsq[threadIdx.x] = 0.0;
}

__global__ void edge_kernel(const float* __restrict__ adj_vals,
                            unsigned ke0, unsigned ke1) {
  int j = blockIdx.x * blockDim.x + threadIdx.x;
  if (j >= N_EDGES) return;
  float u = u01(rbits32(ke0, ke1, (unsigned)j));
  g_vals[j] = (u < 0.6f) ? (adj_vals[j] / 0.6f) : 0.0f;
}

// Fused: RNG (noise + 2 dropouts) + GEMM  h = x @ W
__global__ __launch_bounds__(256, 2)
void gemm_kernel(const float* __restrict__ data, const float* __restrict__ W,
                 unsigned kn0, unsigned kn1,
                 unsigned ka0, unsigned ka1,
                 unsigned kb0, unsigned kb1) {
  __shared__ float As[16][128];
  __shared__ float Bs[16][128];
  int m0  = blockIdx.x * 128;
  int tid = threadIdx.x;
  int tx = tid & 15, ty = tid >> 4;
  int arow = tid >> 1, akq = (tid & 1) * 8;
  int bk = tid >> 4,   bn  = (tid & 15) * 8;
  int rowIdx = m0 + arow;
  bool aok = rowIdx < N_NODES;
  const float* dptr = data + (size_t)rowIdx * D_IN + akq;
  unsigned ibase = (unsigned)rowIdx * (unsigned)D_IN + (unsigned)akq;
  const float* bptr = W + bk * D_H + bn;
  float acc[8][8];
#pragma unroll
  for (int i = 0; i < 8; i++)
#pragma unroll
    for (int j = 0; j < 8; j++) acc[i][j] = 0.0f;

  for (int k0 = 0; k0 < D_IN; k0 += 16) {
    float xv[8];
    if (aok) {
      float4 d0 = *(const float4*)(dptr + k0);
      float4 d1 = *(const float4*)(dptr + k0 + 4);
      float dv[8] = {d0.x, d0.y, d0.z, d0.w, d1.x, d1.y, d1.z, d1.w};
#pragma unroll
      for (int e = 0; e < 8; e++)
        xv[e] = gen_x(dv[e], ibase + (unsigned)(k0 + e),
                      kn0, kn1, ka0, ka1, kb0, kb1);
    } else {
#pragma unroll
      for (int e = 0; e < 8; e++) xv[e] = 0.0f;
    }
    float4 b0 = *(const float4*)(bptr + k0 * D_H);
    float4 b1 = *(const float4*)(bptr + k0 * D_H + 4);
    __syncthreads();
#pragma unroll
    for (int e = 0; e < 8; e++) As[akq + e][arow] = xv[e];
    *(float4*)&Bs[bk][bn]     = b0;
    *(float4*)&Bs[bk][bn + 4] = b1;
    __syncthreads();
#pragma unroll
    for (int kk = 0; kk < 16; kk++) {
      float a[8], b[8];
      *(float4*)(a)     = *(float4*)&As[kk][ty*8];
      *(float4*)(a + 4) = *(float4*)&As[kk][ty*8 + 4];
      *(float4*)(b)     = *(float4*)&Bs[kk][tx*8];
      *(float4*)(b + 4) = *(float4*)&Bs[kk][tx*8 + 4];
#pragma unroll
      for (int i = 0; i < 8; i++)
#pragma unroll
        for (int j = 0; j < 8; j++)
          acc[i][j] = fmaf(a[i], b[j], acc[i][j]);
    }
  }
#pragma unroll
  for (int i = 0; i < 8; i++) {
    int row = m0 + ty * 8 + i;
    if (row < N_NODES) {
      *(float4*)(g_h + (size_t)row * D_H + tx * 8) =
          make_float4(acc[i][0], acc[i][1], acc[i][2], acc[i][3]);
      *(float4*)(g_h + (size_t)row * D_H + tx * 8 + 4) =
          make_float4(acc[i][4], acc[i][5], acc[i][6], acc[i][7]);
    }
  }
}

// adj_indices is int32 [2, E]
__global__ void spmm_kernel(const int* __restrict__ aidx,
                            float* __restrict__ out) {
  int g = blockIdx.x * blockDim.x + threadIdx.x;
  int e = g >> 5;
  int lane = g & 31;
  if (e >= N_EDGES) return;
  float v = g_vals[e];
  if (v == 0.0f) return;
  int row = aidx[e];
  int col = aidx[N_EDGES + e];
  if ((unsigned)row >= (unsigned)N_NODES || (unsigned)col >= (unsigned)N_NODES) return;
  float4 m = *((const float4*)(g_h + (size_t)col * D_H) + lane);
  m.x *= v; m.y *= v; m.z *= v; m.w *= v;
  atomicAdd(((float4*)(out + (size_t)row * D_H)) + lane, m);
}

__device__ __forceinline__ float elu_f(float a) {
  return a > 0.0f ? a : expm1f(a);
}

__global__ void stats_kernel(const float* __restrict__ agg) {
  int c = threadIdx.x & (D_H - 1);
  int r0 = blockIdx.x * 2 + (threadIdx.x >> 7);
  int stride = gridDim.x * 2;
  float s = 0.0f, s2 = 0.0f;
  for (int r = r0; r < N_NODES; r += stride) {
    float f = elu_f(agg[(size_t)r * D_H + c]);
    s += f;
    s2 = fmaf(f, f, s2);
  }
  atomicAdd(&g_sum[c], (double)s);
  atomicAdd(&g_sumsq[c], (double)s2);
}

__global__ void finalize_params_kernel(const float* __restrict__ gamma,
                                       const float* __restrict__ beta) {
  int c = threadIdx.x;
  float mean = (float)(g_sum[c]   * (1.0 / (double)N_NODES));
  float ex2  = (float)(g_sumsq[c] * (1.0 / (double)N_NODES));
  float var  = ex2 - mean * mean;
  float rs = rsqrtf(var + 1e-5f);
  float sc = gamma[c] * rs;
  g_scale[c] = sc;
  g_shift[c] = fmaf(-mean, sc, beta[c]);
}

__global__ void bn_apply_kernel(float* __restrict__ out) {
  int t = blockIdx.x * blockDim.x + threadIdx.x;
  if (t >= NH / 4) return;
  float4 a = ((float4*)out)[t];
  int c = (t * 4) & (D_H - 1);
  a.x = fmaf(elu_f(a.x), g_scale[c + 0], g_shift[c + 0]);
  a.y = fmaf(elu_f(a.y), g_scale[c + 1], g_shift[c + 1]);
  a.z = fmaf(elu_f(a.z), g_scale[c + 2], g_shift[c + 2]);
  a.w = fmaf(elu_f(a.w), g_scale[c + 3], g_shift[c + 3]);
  ((float4*)out)[t] = a;
}

extern "C" void kernel_launch(void* const* d_in, const int* in_sizes, int n_in,
                              void* d_out, int out_size) {
  const float* data  = (const float*)d_in[0];
  const int*   aidx  = (const int*)d_in[1];     // int32 [2, E]
  const float* avals = (const float*)d_in[2];
  const float* W     = (const float*)d_in[3];
  const float* gamma = (const float*)d_in[4];
  const float* beta  = (const float*)d_in[5];
  float* out = (float*)d_out;

  // split(key(42), 4) fold-like: key_j = threefry2x32((0,42),(0,j))
  unsigned keys[4][2];
  for (unsigned j = 0; j < 4; j++) {
    unsigned x0 = 0u, x1 = j;
    tf2x32(0u, 42u, x0, x1);
    keys[j][0] = x0; keys[j][1] = x1;
  }

  cudaMemsetAsync(out, 0, (size_t)NH * sizeof(float), 0);
  zero_stats_kernel<<<1, D_H>>>();
  edge_kernel<<<(N_EDGES + 255) / 256, 256>>>(avals, keys[3][0], keys[3][1]);
  gemm_kernel<<<(N_NODES + 127) / 128, 256>>>(data, W,
      keys[0][0], keys[0][1], keys[1][0], keys[1][1], keys[2][0], keys[2][1]);
  spmm_kernel<<<(N_EDGES * 32 + 255) / 256, 256>>>(aidx, out);
  stats_kernel<<<592, 256>>>(out);
  finalize_params_kernel<<<1, D_H>>>(gamma, beta);
  bn_apply_kernel<<<(NH / 4 + 255) / 256, 256>>>(out);
}

// round 6
// speedup vs baseline: 1.2633x; 1.2633x over previous
#include <cuda_runtime.h>
#include <cstdint>

#define N_NODES 100000
#define D_IN    512
#define D_H     128
#define NX      (N_NODES * D_IN)
#define NH      (N_NODES * D_H)
#define N_EDGES 1600000

__device__ __align__(16) float g_x[NX];
__device__ __align__(16) float g_h[NH];
__device__ __align__(16) float g_vals[N_EDGES];
__device__ double g_sum[D_H];
__device__ double g_sumsq[D_H];
__device__ float  g_scale[D_H];
__device__ float  g_shift[D_H];

__host__ __device__ __forceinline__ void tf2x32(unsigned k0, unsigned k1,
                                                unsigned &x0, unsigned &x1) {
  unsigned k2 = k0 ^ k1 ^ 0x1BD11BDAu;
  x0 += k0; x1 += k1;
#define TFR(r) { x0 += x1; x1 = (x1 << (r)) | (x1 >> (32 - (r))); x1 ^= x0; }
  TFR(13) TFR(15) TFR(26) TFR(6)   x0 += k1; x1 += k2 + 1u;
  TFR(17) TFR(29) TFR(16) TFR(24)  x0 += k2; x1 += k0 + 2u;
  TFR(13) TFR(15) TFR(26) TFR(6)   x0 += k0; x1 += k1 + 3u;
  TFR(17) TFR(29) TFR(16) TFR(24)  x0 += k1; x1 += k2 + 4u;
  TFR(13) TFR(15) TFR(26) TFR(6)   x0 += k2; x1 += k0 + 5u;
#undef TFR
}

__device__ __forceinline__ unsigned rbits32(unsigned k0, unsigned k1, unsigned i) {
  unsigned x0 = 0u, x1 = i;
  tf2x32(k0, k1, x0, x1);
  return x0 ^ x1;
}

__device__ __forceinline__ float u01(unsigned b) {
  return __uint_as_float((b >> 9) | 0x3F800000u) - 1.0f;
}

__device__ __forceinline__ float erfinv_xla(float x) {
  float w = -log1pf(-x * x);
  float p;
  if (w < 5.0f) {
    w -= 2.5f;
    p = 2.81022636e-08f;
    p = fmaf(p, w, 3.43273939e-07f);
    p = fmaf(p, w, -3.5233877e-06f);
    p = fmaf(p, w, -4.39150654e-06f);
    p = fmaf(p, w, 0.00021858087f);
    p = fmaf(p, w, -0.00125372503f);
    p = fmaf(p, w, -0.00417768164f);
    p = fmaf(p, w, 0.246640727f);
    p = fmaf(p, w, 1.50140941f);
  } else {
    w = sqrtf(w) - 3.0f;
    p = -0.000200214257f;
    p = fmaf(p, w, 0.000100950558f);
    p = fmaf(p, w, 0.00134934322f);
    p = fmaf(p, w, -0.00367342844f);
    p = fmaf(p, w, 0.00573950773f);
    p = fmaf(p, w, -0.0076224613f);
    p = fmaf(p, w, 0.00943887047f);
    p = fmaf(p, w, 1.00167406f);
    p = fmaf(p, w, 2.83297682f);
  }
  return p * x;
}

__device__ __forceinline__ float normal32(unsigned b) {
  const float LO = -0.99999994f;
  float f = u01(b);
  float u = fmaxf(LO, f * 2.0f + LO);
  return 1.4142135381698608f * erfinv_xla(u);
}

__global__ void zero_stats_kernel() {
  g_sum[threadIdx.x] = 0.0;
  g_sumsq[threadIdx.x] = 0.0;
}

__global__ void rng_x_kernel(const float* __restrict__ data,
                             unsigned kn0, unsigned kn1,
                             unsigned ka0, unsigned ka1,
                             unsigned kb0, unsigned kb1) {
  int t = blockIdx.x * blockDim.x + threadIdx.x;
  if (t >= NX / 4) return;
  int base = t * 4;
  float4 d = *((const float4*)data + t);
  float dv[4] = {d.x, d.y, d.z, d.w};
  float o[4];
#pragma unroll
  for (int e = 0; e < 4; e++) {
    unsigned i = (unsigned)(base + e);
    unsigned b1 = rbits32(ka0, ka1, i);
    unsigned b2 = rbits32(kb0, kb1, i);
    // keep iff u01(b) < 0.5 for both  <=>  top bit of both is 0
    if (((b1 | b2) & 0x80000000u) == 0u) {
      float n = normal32(rbits32(kn0, kn1, i));
      o[e] = (dv[e] + 0.01f * n) * 4.0f;
    } else {
      o[e] = 0.0f;
    }
  }
  *((float4*)g_x + t) = make_float4(o[0], o[1], o[2], o[3]);
}

__global__ void edge_kernel(const float* __restrict__ adj_vals,
                            unsigned ke0, unsigned ke1) {
  int j = blockIdx.x * blockDim.x + threadIdx.x;
  if (j >= N_EDGES) return;
  unsigned b = rbits32(ke0, ke1, (unsigned)j);
  // keep iff u01(b) < 0.6
  g_vals[j] = (u01(b) < 0.6f) ? (adj_vals[j] / 0.6f) : 0.0f;
}

__global__ __launch_bounds__(256, 2)
void gemm_kernel(const float* __restrict__ W) {
  __shared__ float As[16][128];
  __shared__ float Bs[16][128];
  int m0  = blockIdx.x * 128;
  int tid = threadIdx.x;
  int tx = tid & 15, ty = tid >> 4;
  int arow = tid >> 1, akq = (tid & 1) * 8;
  int bk = tid >> 4,   bn  = (tid & 15) * 8;
  bool aok = (m0 + arow) < N_NODES;
  const float* aptr = g_x + (size_t)(m0 + arow) * D_IN + akq;
  const float* bptr = W + bk * D_H + bn;
  float acc[8][8];
#pragma unroll
  for (int i = 0; i < 8; i++)
#pragma unroll
    for (int j = 0; j < 8; j++) acc[i][j] = 0.0f;

  for (int k0 = 0; k0 < D_IN; k0 += 16) {
    float4 a0 = make_float4(0,0,0,0), a1 = a0;
    if (aok) {
      a0 = *(const float4*)(aptr + k0);
      a1 = *(const float4*)(aptr + k0 + 4);
    }
    float4 b0 = *(const float4*)(bptr + k0 * D_H);
    float4 b1 = *(const float4*)(bptr + k0 * D_H + 4);
    __syncthreads();
    As[akq+0][arow] = a0.x; As[akq+1][arow] = a0.y;
    As[akq+2][arow] = a0.z; As[akq+3][arow] = a0.w;
    As[akq+4][arow] = a1.x; As[akq+5][arow] = a1.y;
    As[akq+6][arow] = a1.z; As[akq+7][arow] = a1.w;
    *(float4*)&Bs[bk][bn]     = b0;
    *(float4*)&Bs[bk][bn + 4] = b1;
    __syncthreads();
#pragma unroll
    for (int kk = 0; kk < 16; kk++) {
      float a[8], b[8];
      *(float4*)(a)     = *(float4*)&As[kk][ty*8];
      *(float4*)(a + 4) = *(float4*)&As[kk][ty*8 + 4];
      *(float4*)(b)     = *(float4*)&Bs[kk][tx*8];
      *(float4*)(b + 4) = *(float4*)&Bs[kk][tx*8 + 4];
#pragma unroll
      for (int i = 0; i < 8; i++)
#pragma unroll
        for (int j = 0; j < 8; j++)
          acc[i][j] = fmaf(a[i], b[j], acc[i][j]);
    }
  }
#pragma unroll
  for (int i = 0; i < 8; i++) {
    int row = m0 + ty * 8 + i;
    if (row < N_NODES) {
      *(float4*)(g_h + (size_t)row * D_H + tx * 8) =
          make_float4(acc[i][0], acc[i][1], acc[i][2], acc[i][3]);
      *(float4*)(g_h + (size_t)row * D_H + tx * 8 + 4) =
          make_float4(acc[i][4], acc[i][5], acc[i][6], acc[i][7]);
    }
  }
}

// 4 edges per warp for MLP: 4 independent gathers + 4 independent float4 atomics
#define EPW 4
__global__ void spmm_kernel(const int* __restrict__ aidx,
                            float* __restrict__ out) {
  int w = (blockIdx.x * blockDim.x + threadIdx.x) >> 5;
  int lane = threadIdx.x & 31;
  int e0 = w * EPW;
  if (e0 >= N_EDGES) return;

  float4 m[EPW];
  int row[EPW];
  bool act[EPW];
#pragma unroll
  for (int i = 0; i < EPW; i++) {
    int e = e0 + i;
    act[i] = false;
    if (e < N_EDGES) {
      float v = g_vals[e];
      if (v != 0.0f) {
        int r = aidx[e];
        int c = aidx[N_EDGES + e];
        if ((unsigned)r < (unsigned)N_NODES && (unsigned)c < (unsigned)N_NODES) {
          float4 t = *((const float4*)(g_h + (size_t)c * D_H) + lane);
          m[i] = make_float4(t.x * v, t.y * v, t.z * v, t.w * v);
          row[i] = r;
          act[i] = true;
        }
      }
    }
  }
#pragma unroll
  for (int i = 0; i < EPW; i++)
    if (act[i])
      atomicAdd(((float4*)(out + (size_t)row[i] * D_H)) + lane, m[i]);
}

__device__ __forceinline__ float elu_f(float a) {
  return a > 0.0f ? a : expm1f(a);
}

__global__ void stats_kernel(const float* __restrict__ agg) {
  int c = threadIdx.x & (D_H - 1);
  int r0 = blockIdx.x * 2 + (threadIdx.x >> 7);
  int stride = gridDim.x * 2;
  float s = 0.0f, s2 = 0.0f;
  for (int r = r0; r < N_NODES; r += stride) {
    float f = elu_f(agg[(size_t)r * D_H + c]);
    s += f;
    s2 = fmaf(f, f, s2);
  }
  atomicAdd(&g_sum[c], (double)s);
  atomicAdd(&g_sumsq[c], (double)s2);
}

__global__ void finalize_params_kernel(const float* __restrict__ gamma,
                                       const float* __restrict__ beta) {
  int c = threadIdx.x;
  float mean = (float)(g_sum[c]   * (1.0 / (double)N_NODES));
  float ex2  = (float)(g_sumsq[c] * (1.0 / (double)N_NODES));
  float var  = ex2 - mean * mean;
  float rs = rsqrtf(var + 1e-5f);
  float sc = gamma[c] * rs;
  g_scale[c] = sc;
  g_shift[c] = fmaf(-mean, sc, beta[c]);
}

__global__ void bn_apply_kernel(float* __restrict__ out) {
  int t = blockIdx.x * blockDim.x + threadIdx.x;
  if (t >= NH / 4) return;
  float4 a = ((float4*)out)[t];
  int c = (t * 4) & (D_H - 1);
  a.x = fmaf(elu_f(a.x), g_scale[c + 0], g_shift[c + 0]);
  a.y = fmaf(elu_f(a.y), g_scale[c + 1], g_shift[c + 1]);
  a.z = fmaf(elu_f(a.z), g_scale[c + 2], g_shift[c + 2]);
  a.w = fmaf(elu_f(a.w), g_scale[c + 3], g_shift[c + 3]);
  ((float4*)out)[t] = a;
}

extern "C" void kernel_launch(void* const* d_in, const int* in_sizes, int n_in,
                              void* d_out, int out_size) {
  const float* data  = (const float*)d_in[0];
  const int*   aidx  = (const int*)d_in[1];     // int32 [2, E]
  const float* avals = (const float*)d_in[2];
  const float* W     = (const float*)d_in[3];
  const float* gamma = (const float*)d_in[4];
  const float* beta  = (const float*)d_in[5];
  float* out = (float*)d_out;

  unsigned keys[4][2];
  for (unsigned j = 0; j < 4; j++) {
    unsigned x0 = 0u, x1 = j;
    tf2x32(0u, 42u, x0, x1);
    keys[j][0] = x0; keys[j][1] = x1;
  }

  cudaMemsetAsync(out, 0, (size_t)NH * sizeof(float), 0);
  zero_stats_kernel<<<1, D_H>>>();
  rng_x_kernel<<<(NX / 4 + 255) / 256, 256>>>(data,
      keys[0][0], keys[0][1], keys[1][0], keys[1][1], keys[2][0], keys[2][1]);
  edge_kernel<<<(N_EDGES + 255) / 256, 256>>>(avals, keys[3][0], keys[3][1]);
  gemm_kernel<<<(N_NODES + 127) / 128, 256>>>(W);
  {
    int warps = (N_EDGES + EPW - 1) / EPW;
    spmm_kernel<<<(warps * 32 + 255) / 256, 256>>>(aidx, out);
  }
  stats_kernel<<<592, 256>>>(out);
  finalize_params_kernel<<<1, D_H>>>(gamma, beta);
  bn_apply_kernel<<<(NH / 4 + 255) / 256, 256>>>(out);
}